// round 3
// baseline (speedup 1.0000x reference)
#include <cuda_runtime.h>
#include <cstdint>

#define D 128
#define NVOX (D * D * D)
#define BT 8                 // block tile edge
#define TPB (BT * BT * BT)   // 512
#define HT 10                // halo tile edge
#define FULL 0xFFFFFFFFu

__global__ void __launch_bounds__(TPB)
ca_update_kernel(const float* __restrict__ x,
                 const float* __restrict__ out,
                 float* __restrict__ y)
{
    __shared__ __align__(16) float se[HT * HT * HT * 3]; // halo euler
    __shared__ float ss[TPB];                            // center state0
    __shared__ __align__(16) float ly[TPB * 5];          // output staging

    const int tid = threadIdx.x;
    const int li = tid >> 6;
    const int lj = (tid >> 3) & 7;
    const int lk = tid & 7;
    const int i0 = blockIdx.z * BT;
    const int j0 = blockIdx.y * BT;
    const int k0 = blockIdx.x * BT;

    // ---- phase 1: zero halo tile (covers out-of-volume padding) ----
    for (int t = tid; t < HT * HT * HT * 3; t += TPB) se[t] = 0.0f;
    __syncthreads();

    // ---- phase 2: load halo rows coalesced (float4), scatter to smem ----
    // 100 (hi,hj) rows x 14 float4 units
    const int kstart = max(k0 - 1, 0);
    const int kend   = min(k0 + BT + 1, D);
    for (int u = tid; u < 100 * 14; u += TPB) {
        int r  = u / 14;
        int t4 = u - r * 14;
        int hi = r / 10, hj = r - (r / 10) * 10;
        int ii = i0 + hi - 1;
        int jj = j0 + hj - 1;
        if ((unsigned)ii >= (unsigned)D || (unsigned)jj >= (unsigned)D) continue;
        int rowelem = ((ii * D + jj) * D + kstart) * 5;
        int cnt     = (kend - kstart) * 5;
        int a0 = rowelem & ~3;
        int e  = a0 + t4 * 4;
        if (e >= rowelem + cnt) continue;
        float4 q = *reinterpret_cast<const float4*>(x + e);
        float qq[4] = {q.x, q.y, q.z, q.w};
        #pragma unroll
        for (int c = 0; c < 4; c++) {
            int ge = e + c;
            int rel = ge - rowelem;
            if (rel < 0 || rel >= cnt) continue;
            int kv   = rel / 5;          // voxel within [kstart, kend)
            int comp = rel - kv * 5;
            int hk   = kstart + kv - (k0 - 1);   // halo coord 0..9
            if (comp >= 1 && comp <= 3) {
                se[((hi * HT + hj) * HT + hk) * 3 + (comp - 1)] = qq[c];
            } else if (comp == 0 &&
                       hi >= 1 && hi < 9 && hj >= 1 && hj < 9 &&
                       hk >= 1 && hk < 9) {
                ss[((hi - 1) * BT + (hj - 1)) * BT + (hk - 1)] = qq[c];
            }
        }
    }
    __syncthreads();

    // ---- phase 3: per-voxel update ----
    const int gi = i0 + li, gj = j0 + lj, gk = k0 + lk;
    const int v  = (gi * D + gj) * D + gk;

    const float4* o4 = reinterpret_cast<const float4*>(out + (size_t)v * 8);
    float4 oa = o4[0];
    float4 ob = o4[1];

    int   state1 = 0;
    float bst    = oa.x;
    if (oa.y > bst) { bst = oa.y; state1 = 1; }
    if (oa.z > bst) { bst = oa.z; state1 = 2; }
    if (oa.w > bst) { bst = oa.w; state1 = 3; }

    int state0 = (int)ss[tid];
    if (state0 == 0) state1 = 0;

    const int cbase = (((li + 1) * HT + (lj + 1)) * HT + (lk + 1)) * 3;
    float y_e0 = se[cbase + 0];
    float y_e1 = se[cbase + 1];
    float y_e2 = se[cbase + 2];

    float field1 = ob.w;
    if (state1 <= 1) {
        field1 = -1.0f;
        y_e0 = -1.0f; y_e1 = -1.0f; y_e2 = -1.0f;
    } else if (state1 == 2) {
        field1 = fminf(fmaxf(field1, 0.0f), 0.92f);
    } else {
        field1 = 1.0f;
    }

    // ---- phase 4: warp-cooperative neighbor argmin from smem ----
    const int lane = tid & 31;
    bool flag = (state0 <= 1) && (state1 > 1);
    unsigned mask = __ballot_sync(FULL, flag);

    // lane -> lexicographic neighbor offset (center skipped)
    int c26  = lane + (lane >= 13 ? 1 : 0);
    int di = c26 / 9 - 1;
    int dj = (c26 / 3) % 3 - 1;
    int dk = c26 % 3 - 1;
    int noff = (di * (HT * HT) + dj * HT + dk) * 3;

    while (mask) {
        int src = __ffs(mask) - 1;
        mask &= mask - 1;

        int   cb = __shfl_sync(FULL, cbase, src);
        float rx = __shfl_sync(FULL, ob.x,  src);
        float ry = __shfl_sync(FULL, ob.y,  src);
        float rz = __shfl_sync(FULL, ob.z,  src);

        float n0 = 0.0f, n1 = 0.0f, n2 = 0.0f;
        if (lane < 26) {
            const float* nb = se + cb + noff;
            n0 = nb[0]; n1 = nb[1]; n2 = nb[2];
        }
        float d0 = n0 - rx;
        float d1 = n1 - ry;
        float d2 = n2 - rz;
        float dist = d0 * d0 + d1 * d1 + d2 * d2;

        unsigned bits = (lane < 26) ? __float_as_uint(dist) : 0xFFFFFFFFu;
        unsigned dmin = __reduce_min_sync(FULL, bits);
        unsigned win  = __ballot_sync(FULL, bits == dmin);
        int s = __ffs(win) - 1;

        float w0 = __shfl_sync(FULL, n0, s);
        float w1 = __shfl_sync(FULL, n1, s);
        float w2 = __shfl_sync(FULL, n2, s);
        if (lane == src) { y_e0 = w0; y_e1 = w1; y_e2 = w2; }
    }

    // ---- phase 5: stage outputs, write coalesced float4 rows ----
    ly[tid * 5 + 0] = (float)state1;
    ly[tid * 5 + 1] = y_e0;
    ly[tid * 5 + 2] = y_e1;
    ly[tid * 5 + 3] = y_e2;
    ly[tid * 5 + 4] = field1;
    __syncthreads();

    // 64 (i,j) rows x 40 floats = 10 float4 each; base is 16B-aligned
    for (int f = tid; f < 64 * 10; f += TPB) {
        int row  = f / 10;
        int part = f - row * 10;
        int ri = i0 + (row >> 3);
        int rj = j0 + (row & 7);
        int gbase = ((ri * D + rj) * D + k0) * 5 + part * 4;
        *reinterpret_cast<float4*>(y + gbase) =
            *reinterpret_cast<const float4*>(&ly[row * 40 + part * 4]);
    }
}

extern "C" void kernel_launch(void* const* d_in, const int* in_sizes, int n_in,
                              void* d_out, int out_size)
{
    const float* x   = (const float*)d_in[0];
    const float* out = (const float*)d_in[1];
    if (n_in >= 2 && in_sizes[0] == 8 * NVOX && in_sizes[1] == 5 * NVOX) {
        const float* t = x; x = out; out = t;
    }
    float* y = (float*)d_out;

    dim3 grid(D / BT, D / BT, D / BT);
    ca_update_kernel<<<grid, TPB>>>(x, out, y);
}

// round 4
// speedup vs baseline: 1.0932x; 1.0932x over previous
#include <cuda_runtime.h>
#include <cstdint>

#define D 128
#define NVOX (D * D * D)
#define BT 8
#define TPB 512
#define FULL 0xFFFFFFFFu

__global__ void __launch_bounds__(TPB, 2)
ca_update_kernel(const float* __restrict__ x,
                 const float* __restrict__ out,
                 float* __restrict__ y)
{
    __shared__ float se[3][1000];                 // euler halo, SoA planes (10^3)
    __shared__ float ss[TPB];                     // center state0
    __shared__ __align__(16) float ly[TPB * 5];   // output staging

    const int tid  = threadIdx.x;
    const int warp = tid >> 5;
    const int lane = tid & 31;
    const int i0 = blockIdx.z * BT;
    const int j0 = blockIdx.y * BT;
    const int k0 = blockIdx.x * BT;

    // ---- halo load: one warp per (hi,hj) row, one LDG per row ----
    // lane l<30: voxel vox=l/3 of the row, euler component l%3
    const int vox  = lane / 3;          // 0..9 (lane<30)
    const int comp = lane - vox * 3;    // 0..2
    for (int r = warp; r < 100; r += TPB / 32) {
        int hi = r / 10;
        int hj = r - hi * 10;
        int ii = i0 + hi - 1;
        int jj = j0 + hj - 1;
        bool rowok = ((unsigned)ii < (unsigned)D) & ((unsigned)jj < (unsigned)D);
        // base element of voxel (ii,jj,k0-1); only dereferenced when lane valid
        const float* rowp = x + (((long)ii * D + jj) * D + (k0 - 1)) * 5;

        int  kk     = k0 - 1 + vox;
        bool laneok = rowok && ((unsigned)kk < (unsigned)D) && (lane < 30);
        float val = laneok ? rowp[vox * 5 + comp + 1] : 0.0f;
        if (lane < 30) se[comp][r * 10 + vox] = val;

        // state0 for interior voxels (same cache lines -> L1 hits)
        if (rowok && hi >= 1 && hi <= 8 && hj >= 1 && hj <= 8 &&
            lane >= 1 && lane <= 8) {
            ss[((hi - 1) * 8 + (hj - 1)) * 8 + (lane - 1)] = rowp[lane * 5];
        }
    }
    __syncthreads();

    // ---- per-voxel update ----
    const int li = tid >> 6;
    const int lj = (tid >> 3) & 7;
    const int lk = tid & 7;
    const int v  = (((i0 + li) * D + (j0 + lj)) * D + (k0 + lk));

    const float4* o4 = reinterpret_cast<const float4*>(out + (size_t)v * 8);
    float4 oa = o4[0];
    float4 ob = o4[1];

    int   state1 = 0;
    float bst    = oa.x;
    if (oa.y > bst) { bst = oa.y; state1 = 1; }
    if (oa.z > bst) { bst = oa.z; state1 = 2; }
    if (oa.w > bst) { bst = oa.w; state1 = 3; }

    int state0 = (int)ss[tid];
    if (state0 == 0) state1 = 0;

    const int cb = (li + 1) * 100 + (lj + 1) * 10 + (lk + 1);
    float y_e0 = se[0][cb];
    float y_e1 = se[1][cb];
    float y_e2 = se[2][cb];

    float field1 = ob.w;
    if (state1 <= 1) {
        field1 = -1.0f;
        y_e0 = -1.0f; y_e1 = -1.0f; y_e2 = -1.0f;
    } else if (state1 == 2) {
        field1 = fminf(fmaxf(field1, 0.0f), 0.92f);
    } else {
        field1 = 1.0f;
    }

    // ---- warp-cooperative neighbor argmin from smem ----
    bool flag = (state0 <= 1) && (state1 > 1);
    unsigned mask = __ballot_sync(FULL, flag);

    // lane -> lexicographic (di,dj,dk), center skipped
    int c26 = lane + (lane >= 13 ? 1 : 0);
    int di = c26 / 9 - 1;
    int dj = (c26 / 3) % 3 - 1;
    int dk = c26 % 3 - 1;
    int noff = di * 100 + dj * 10 + dk;

    while (mask) {
        int src = __ffs(mask) - 1;
        mask &= mask - 1;

        int   scb = __shfl_sync(FULL, cb,   src);
        float rx  = __shfl_sync(FULL, ob.x, src);
        float ry  = __shfl_sync(FULL, ob.y, src);
        float rz  = __shfl_sync(FULL, ob.z, src);

        float n0 = 0.0f, n1 = 0.0f, n2 = 0.0f;
        if (lane < 26) {
            int a = scb + noff;
            n0 = se[0][a];
            n1 = se[1][a];
            n2 = se[2][a];
        }
        float d0 = n0 - rx;
        float d1 = n1 - ry;
        float d2 = n2 - rz;
        float dist = d0 * d0 + d1 * d1 + d2 * d2;

        unsigned bits = (lane < 26) ? __float_as_uint(dist) : 0xFFFFFFFFu;
        unsigned dmin = __reduce_min_sync(FULL, bits);
        unsigned win  = __ballot_sync(FULL, bits == dmin);
        int s = __ffs(win) - 1;

        float w0 = __shfl_sync(FULL, n0, s);
        float w1 = __shfl_sync(FULL, n1, s);
        float w2 = __shfl_sync(FULL, n2, s);
        if (lane == src) { y_e0 = w0; y_e1 = w1; y_e2 = w2; }
    }

    // ---- stage + coalesced float4 output ----
    ly[tid * 5 + 0] = (float)state1;
    ly[tid * 5 + 1] = y_e0;
    ly[tid * 5 + 2] = y_e1;
    ly[tid * 5 + 3] = y_e2;
    ly[tid * 5 + 4] = field1;
    __syncthreads();

    // 64 (i,j) rows x 10 float4 (40 floats, base 16B-aligned since k0%8==0)
    for (int f = tid; f < 64 * 10; f += TPB) {
        int row  = f / 10;
        int part = f - row * 10;
        int ri = i0 + (row >> 3);
        int rj = j0 + (row & 7);
        long gbase = (((long)ri * D + rj) * D + k0) * 5 + part * 4;
        *reinterpret_cast<float4*>(y + gbase) =
            *reinterpret_cast<const float4*>(&ly[row * 40 + part * 4]);
    }
}

extern "C" void kernel_launch(void* const* d_in, const int* in_sizes, int n_in,
                              void* d_out, int out_size)
{
    const float* x   = (const float*)d_in[0];
    const float* out = (const float*)d_in[1];
    if (n_in >= 2 && in_sizes[0] == 8 * NVOX && in_sizes[1] == 5 * NVOX) {
        const float* t = x; x = out; out = t;
    }
    float* y = (float*)d_out;

    dim3 grid(D / BT, D / BT, D / BT);
    ca_update_kernel<<<grid, TPB>>>(x, out, y);
}

// round 5
// speedup vs baseline: 1.6602x; 1.5186x over previous
#include <cuda_runtime.h>
#include <cstdint>

#define D 128
#define NVOX (D * D * D)
#define P 130
#define PV (P * P * P)
#define FULL 0xFFFFFFFFu

__device__ float g_e0[PV];
__device__ float g_e1[PV];
__device__ float g_e2[PV];
__device__ float g_s[NVOX];

// ---------- pass 1: transpose euler to zero-padded SoA, state0 compact ----------
__global__ void __launch_bounds__(256)
transpose_kernel(const float* __restrict__ x)
{
    int pv = blockIdx.x * blockDim.x + threadIdx.x;
    if (pv >= PV) return;

    int pk = pv % P;
    int pj = (pv / P) % P;
    int pi = pv / (P * P);

    int i = pi - 1, j = pj - 1, k = pk - 1;
    bool in = ((unsigned)i < (unsigned)D) &
              ((unsigned)j < (unsigned)D) &
              ((unsigned)k < (unsigned)D);

    float e0 = 0.0f, e1 = 0.0f, e2 = 0.0f;
    if (in) {
        long v = ((long)i * D + j) * D + k;
        const float* xv = x + v * 5;
        g_s[v] = xv[0];
        e0 = xv[1]; e1 = xv[2]; e2 = xv[3];
    }
    g_e0[pv] = e0;
    g_e1[pv] = e1;
    g_e2[pv] = e2;
}

// ---------- pass 2: per-voxel update with cooperative SoA gather ----------
__global__ void __launch_bounds__(256)
ca_update_kernel(const float* __restrict__ out, float* __restrict__ y)
{
    __shared__ __align__(16) float ly[256 * 5];

    const int tid  = threadIdx.x;
    const int base = blockIdx.x * 256;
    const int v    = base + tid;
    const int lane = tid & 31;

    const int k = v & (D - 1);
    const int j = (v >> 7) & (D - 1);
    const int i = v >> 14;
    const int pc = ((i + 1) * P + (j + 1)) * P + (k + 1);  // padded center

    const float4* o4 = reinterpret_cast<const float4*>(out + (size_t)v * 8);
    float4 oa = o4[0];
    float4 ob = o4[1];

    int   state1 = 0;
    float bst    = oa.x;
    if (oa.y > bst) { bst = oa.y; state1 = 1; }
    if (oa.z > bst) { bst = oa.z; state1 = 2; }
    if (oa.w > bst) { bst = oa.w; state1 = 3; }

    int state0 = (int)g_s[v];
    if (state0 == 0) state1 = 0;

    float y_e0 = g_e0[pc];
    float y_e1 = g_e1[pc];
    float y_e2 = g_e2[pc];

    float field1 = ob.w;
    if (state1 <= 1) {
        field1 = -1.0f;
        y_e0 = -1.0f; y_e1 = -1.0f; y_e2 = -1.0f;
    } else if (state1 == 2) {
        field1 = fminf(fmaxf(field1, 0.0f), 0.92f);
    } else {
        field1 = 1.0f;
    }

    // warp-cooperative 26-neighbor argmin (lex order, first occurrence)
    bool flag = (state0 <= 1) && (state1 > 1);
    unsigned mask = __ballot_sync(FULL, flag);

    int c26 = lane + (lane >= 13 ? 1 : 0);
    int di = c26 / 9 - 1;
    int dj = (c26 / 3) % 3 - 1;
    int dk = c26 % 3 - 1;
    int noff = (di * P + dj) * P + dk;

    while (mask) {
        int src = __ffs(mask) - 1;
        mask &= mask - 1;

        int   spc = __shfl_sync(FULL, pc,   src);
        float rx  = __shfl_sync(FULL, ob.x, src);
        float ry  = __shfl_sync(FULL, ob.y, src);
        float rz  = __shfl_sync(FULL, ob.z, src);

        float n0 = 0.0f, n1 = 0.0f, n2 = 0.0f;
        if (lane < 26) {
            int a = spc + noff;
            n0 = g_e0[a];
            n1 = g_e1[a];
            n2 = g_e2[a];
        }
        float d0 = n0 - rx;
        float d1 = n1 - ry;
        float d2 = n2 - rz;
        float dist = d0 * d0 + d1 * d1 + d2 * d2;

        unsigned bits = (lane < 26) ? __float_as_uint(dist) : 0xFFFFFFFFu;
        unsigned dmin = __reduce_min_sync(FULL, bits);
        unsigned win  = __ballot_sync(FULL, bits == dmin);
        int s = __ffs(win) - 1;

        float w0 = __shfl_sync(FULL, n0, s);
        float w1 = __shfl_sync(FULL, n1, s);
        float w2 = __shfl_sync(FULL, n2, s);
        if (lane == src) { y_e0 = w0; y_e1 = w1; y_e2 = w2; }
    }

    // staged coalesced float4 output
    ly[tid * 5 + 0] = (float)state1;
    ly[tid * 5 + 1] = y_e0;
    ly[tid * 5 + 2] = y_e1;
    ly[tid * 5 + 3] = y_e2;
    ly[tid * 5 + 4] = field1;
    __syncthreads();
    {
        float4* yb = reinterpret_cast<float4*>(y + (size_t)base * 5);
        const float4* s4 = reinterpret_cast<const float4*>(ly);
        #pragma unroll
        for (int t = tid; t < 256 * 5 / 4; t += 256) yb[t] = s4[t];
    }
}

extern "C" void kernel_launch(void* const* d_in, const int* in_sizes, int n_in,
                              void* d_out, int out_size)
{
    const float* x   = (const float*)d_in[0];
    const float* out = (const float*)d_in[1];
    if (n_in >= 2 && in_sizes[0] == 8 * NVOX && in_sizes[1] == 5 * NVOX) {
        const float* t = x; x = out; out = t;
    }
    float* y = (float*)d_out;

    transpose_kernel<<<(PV + 255) / 256, 256>>>(x);
    ca_update_kernel<<<NVOX / 256, 256>>>(out, y);
}

// round 6
// speedup vs baseline: 1.8666x; 1.1244x over previous
#include <cuda_runtime.h>
#include <cstdint>

#define D 128
#define NVOX (D * D * D)
#define P 130
#define PV (P * P * P)
#define FULL 0xFFFFFFFFu

// zero-padded SoA: (e0, e1, e2, state0) per voxel
__device__ float4 g_pack[PV];

// ---------- pass 1: transpose x into padded packed SoA ----------
__global__ void __launch_bounds__(256)
transpose_kernel(const float* __restrict__ x)
{
    int pv = blockIdx.x * blockDim.x + threadIdx.x;
    if (pv >= PV) return;

    int pk = pv % P;
    int t  = pv / P;
    int pj = t % P;
    int pi = t / P;

    int i = pi - 1, j = pj - 1, k = pk - 1;
    float4 r = make_float4(0.0f, 0.0f, 0.0f, 0.0f);
    if (((unsigned)i < (unsigned)D) &
        ((unsigned)j < (unsigned)D) &
        ((unsigned)k < (unsigned)D)) {
        const float* xv = x + (((long)i * D + j) * D + k) * 5;
        r.x = xv[1];
        r.y = xv[2];
        r.z = xv[3];
        r.w = xv[0];
    }
    g_pack[pv] = r;
}

// ---------- pass 2: per-voxel update, cooperative packed gather ----------
__global__ void __launch_bounds__(256)
ca_update_kernel(const float* __restrict__ out, float* __restrict__ y)
{
    __shared__ __align__(16) float ly[256 * 5];

    const int tid  = threadIdx.x;
    const int base = blockIdx.x * 256;
    const int v    = base + tid;
    const int lane = tid & 31;

    const int k = v & (D - 1);
    const int j = (v >> 7) & (D - 1);
    const int i = v >> 14;
    const int pc = ((i + 1) * P + (j + 1)) * P + (k + 1);

    const float4* o4 = reinterpret_cast<const float4*>(out + (size_t)v * 8);
    float4 oa = o4[0];
    float4 ob = o4[1];

    int   state1 = 0;
    float bst    = oa.x;
    if (oa.y > bst) { bst = oa.y; state1 = 1; }
    if (oa.z > bst) { bst = oa.z; state1 = 2; }
    if (oa.w > bst) { bst = oa.w; state1 = 3; }

    float4 ctr = g_pack[pc];
    int state0 = (int)ctr.w;
    if (state0 == 0) state1 = 0;

    float y_e0 = ctr.x;
    float y_e1 = ctr.y;
    float y_e2 = ctr.z;

    float field1 = ob.w;
    if (state1 <= 1) {
        field1 = -1.0f;
        y_e0 = -1.0f; y_e1 = -1.0f; y_e2 = -1.0f;
    } else if (state1 == 2) {
        field1 = fminf(fmaxf(field1, 0.0f), 0.92f);
    } else {
        field1 = 1.0f;
    }

    // warp-cooperative 26-neighbor argmin (lex order, first occurrence)
    bool flag = (state0 <= 1) && (state1 > 1);
    unsigned mask = __ballot_sync(FULL, flag);

    int c26 = lane + (lane >= 13 ? 1 : 0);
    int di = c26 / 9 - 1;
    int dj = (c26 / 3) % 3 - 1;
    int dk = c26 % 3 - 1;
    int noff = (di * P + dj) * P + dk;

    while (mask) {
        int src = __ffs(mask) - 1;
        mask &= mask - 1;

        int   spc = __shfl_sync(FULL, pc,   src);
        float rx  = __shfl_sync(FULL, ob.x, src);
        float ry  = __shfl_sync(FULL, ob.y, src);
        float rz  = __shfl_sync(FULL, ob.z, src);

        float n0 = 0.0f, n1 = 0.0f, n2 = 0.0f;
        if (lane < 26) {
            float4 nb = g_pack[spc + noff];   // single LDG.128
            n0 = nb.x; n1 = nb.y; n2 = nb.z;
        }
        float d0 = n0 - rx;
        float d1 = n1 - ry;
        float d2 = n2 - rz;
        float dist = d0 * d0 + d1 * d1 + d2 * d2;

        unsigned bits = (lane < 26) ? __float_as_uint(dist) : 0xFFFFFFFFu;
        unsigned dmin = __reduce_min_sync(FULL, bits);
        unsigned win  = __ballot_sync(FULL, bits == dmin);
        int s = __ffs(win) - 1;

        float w0 = __shfl_sync(FULL, n0, s);
        float w1 = __shfl_sync(FULL, n1, s);
        float w2 = __shfl_sync(FULL, n2, s);
        if (lane == src) { y_e0 = w0; y_e1 = w1; y_e2 = w2; }
    }

    // staged coalesced float4 output
    ly[tid * 5 + 0] = (float)state1;
    ly[tid * 5 + 1] = y_e0;
    ly[tid * 5 + 2] = y_e1;
    ly[tid * 5 + 3] = y_e2;
    ly[tid * 5 + 4] = field1;
    __syncthreads();
    {
        float4* yb = reinterpret_cast<float4*>(y + (size_t)base * 5);
        const float4* s4 = reinterpret_cast<const float4*>(ly);
        #pragma unroll
        for (int t = tid; t < 256 * 5 / 4; t += 256) yb[t] = s4[t];
    }
}

extern "C" void kernel_launch(void* const* d_in, const int* in_sizes, int n_in,
                              void* d_out, int out_size)
{
    const float* x   = (const float*)d_in[0];
    const float* out = (const float*)d_in[1];
    if (n_in >= 2 && in_sizes[0] == 8 * NVOX && in_sizes[1] == 5 * NVOX) {
        const float* t = x; x = out; out = t;
    }
    float* y = (float*)d_out;

    transpose_kernel<<<(PV + 255) / 256, 256>>>(x);
    ca_update_kernel<<<NVOX / 256, 256>>>(out, y);
}